// round 11
// baseline (speedup 1.0000x reference)
#include <cuda_runtime.h>
#include <cuda_fp16.h>

#define HID 5
#define HDIM 2048
#define BSZ 16384

__device__ int g_lengths[BSZ];

// ---------------------------------------------------------------------------
// Kernel 1: per-row nonzero count (ragged length, matches reference mask)
// ---------------------------------------------------------------------------
__global__ void len_kernel(const float* __restrict__ x) {
    int b = blockIdx.x;
    const float4* row = reinterpret_cast<const float4*>(x + (size_t)b * HDIM);
    int tid = threadIdx.x;
    int cnt = 0;
#pragma unroll
    for (int i = 0; i < 2; i++) {
        float4 v = row[tid + i * 256];
        cnt += (v.x != 0.f) + (v.y != 0.f) + (v.z != 0.f) + (v.w != 0.f);
    }
    __shared__ int s[8];
#pragma unroll
    for (int o = 16; o > 0; o >>= 1) cnt += __shfl_down_sync(0xffffffffu, cnt, o);
    if ((tid & 31) == 0) s[tid >> 5] = cnt;
    __syncthreads();
    if (tid < 8) {
        int v = s[tid];
#pragma unroll
        for (int o = 4; o > 0; o >>= 1) v += __shfl_down_sync(0xffu, v, o);
        if (tid == 0) g_lengths[b] = v;
    }
}

// ---------------------------------------------------------------------------
// math helpers
// ---------------------------------------------------------------------------
__device__ __forceinline__ float fast_tanh(float v) {
    float r; asm("tanh.approx.f32 %0, %1;" : "=f"(r) : "f"(v)); return r;
}
__device__ __forceinline__ __half2 tanh2(__half2 v) {
    unsigned u = *reinterpret_cast<unsigned*>(&v), r;
    asm("tanh.approx.f16x2 %0, %1;" : "=r"(r) : "r"(u));
    return *reinterpret_cast<__half2*>(&r);
}

// ---------------------------------------------------------------------------
// LSTM: 2 sequences per thread, interleaved so the fma-heavy GEMV of one
// overlaps the MUFU-heavy epilogue of the other (pipes no longer serialize).
// Gate GEMV fp16 HFMA2, pairs P_u={0.5i,0.5f}, Q_u={0.5o, g};
// sigmoids + tanh(g) from f16x2 tanh; cn / tanh(cn) / h fp32.
// ---------------------------------------------------------------------------
struct State {
    __half2 h2[HID];
    float   c[HID];
    float   h[HID];
};

__device__ __forceinline__ void lstm_step2(State& sA, State& sB,
    float xvA, float xvB, bool updA, bool updB,
    const __half2* __restrict__ wihP, const __half2* __restrict__ wihQ,
    const __half2* __restrict__ bsP,  const __half2* __restrict__ bsQ,
    const __half2 (*whhP)[HID], const __half2 (*whhQ)[HID])
{
    const __half2 xA = __float2half2_rn(xvA);
    const __half2 xB = __float2half2_rn(xvB);
    __half2 aPA[HID], aQA[HID], aPB[HID], aQB[HID];
#pragma unroll
    for (int u = 0; u < HID; u++) {
        __half2 pa = __hfma2(xA, wihP[u], bsP[u]);
        __half2 qa = __hfma2(xA, wihQ[u], bsQ[u]);
        __half2 pb = __hfma2(xB, wihP[u], bsP[u]);
        __half2 qb = __hfma2(xB, wihQ[u], bsQ[u]);
#pragma unroll
        for (int j = 0; j < HID; j++) {
            pa = __hfma2(sA.h2[j], whhP[u][j], pa);
            qa = __hfma2(sA.h2[j], whhQ[u][j], qa);
            pb = __hfma2(sB.h2[j], whhP[u][j], pb);
            qb = __hfma2(sB.h2[j], whhQ[u][j], qb);
        }
        aPA[u] = pa; aQA[u] = qa; aPB[u] = pb; aQB[u] = qb;
    }

    const __half2 h05 = __float2half2_rn(0.5f);
#pragma unroll
    for (int u = 0; u < HID; u++) {
        // seq A
        {
            const __half2 tP = tanh2(aPA[u]);
            const __half2 tQ = tanh2(aQA[u]);
            const __half2 sP = __hfma2(tP, h05, h05);
            const float ig = __low2float(sP);
            const float fg = __high2float(sP);
            const float og = fmaf(__low2float(tQ), 0.5f, 0.5f);
            const float tg = __high2float(tQ);
            const float cn = fmaf(fg, sA.c[u], ig * tg);
            const float hn = og * fast_tanh(cn);
            if (updA) { sA.c[u] = cn; sA.h[u] = hn; sA.h2[u] = __float2half2_rn(hn); }
        }
        // seq B
        {
            const __half2 tP = tanh2(aPB[u]);
            const __half2 tQ = tanh2(aQB[u]);
            const __half2 sP = __hfma2(tP, h05, h05);
            const float ig = __low2float(sP);
            const float fg = __high2float(sP);
            const float og = fmaf(__low2float(tQ), 0.5f, 0.5f);
            const float tg = __high2float(tQ);
            const float cn = fmaf(fg, sB.c[u], ig * tg);
            const float hn = og * fast_tanh(cn);
            if (updB) { sB.c[u] = cn; sB.h[u] = hn; sB.h2[u] = __float2half2_rn(hn); }
        }
    }
}

__global__ void __launch_bounds__(64, 1) lstm_kernel(
    const float* __restrict__ x,
    const float* __restrict__ W_ih,
    const float* __restrict__ W_hh,
    const float* __restrict__ b_ih,
    const float* __restrict__ b_hh,
    float* __restrict__ out)
{
    const int tid = blockIdx.x * blockDim.x + threadIdx.x;
    const int bA = 2 * tid, bB = 2 * tid + 1;

    // gate rows: i:0-4  f:5-9  g:10-14  o:15-19
    __half2 wihP[HID], wihQ[HID], bsP[HID], bsQ[HID];
    __half2 whhP[HID][HID], whhQ[HID][HID];
#pragma unroll
    for (int u = 0; u < HID; u++) {
        const int ri = u, rf = HID + u, rg = 2 * HID + u, ro = 3 * HID + u;
        wihP[u] = __floats2half2_rn(0.5f * W_ih[ri], 0.5f * W_ih[rf]);
        wihQ[u] = __floats2half2_rn(0.5f * W_ih[ro], W_ih[rg]);
        bsP[u]  = __floats2half2_rn(0.5f * (b_ih[ri] + b_hh[ri]),
                                    0.5f * (b_ih[rf] + b_hh[rf]));
        bsQ[u]  = __floats2half2_rn(0.5f * (b_ih[ro] + b_hh[ro]),
                                    (b_ih[rg] + b_hh[rg]));
#pragma unroll
        for (int j = 0; j < HID; j++) {
            whhP[u][j] = __floats2half2_rn(0.5f * W_hh[ri * HID + j],
                                           0.5f * W_hh[rf * HID + j]);
            whhQ[u][j] = __floats2half2_rn(0.5f * W_hh[ro * HID + j],
                                           W_hh[rg * HID + j]);
        }
    }

    const int lenA = g_lengths[bA];
    const int lenB = g_lengths[bB];
    const int lmax = max(lenA, lenB);
    const float* rowA = x + (size_t)bA * HDIM;
    const float* rowB = x + (size_t)bB * HDIM;

    State sA, sB;
#pragma unroll
    for (int u = 0; u < HID; u++) {
        sA.h2[u] = __float2half2_rn(0.f); sA.c[u] = 0.f; sA.h[u] = 0.f;
        sB.h2[u] = __float2half2_rn(0.f); sB.c[u] = 0.f; sB.h[u] = 0.f;
    }

    float4 a0 = make_float4(0.f, 0.f, 0.f, 0.f), b0 = a0;
    if (lmax > 0) {
        a0 = *reinterpret_cast<const float4*>(rowA);
        b0 = *reinterpret_cast<const float4*>(rowB);
    }

    for (int t0 = 0; t0 < lmax; t0 += 4) {
        float4 nA = a0, nB = b0;
        const int nt = t0 + 4;
        if (nt < HDIM) {
            nA = *reinterpret_cast<const float4*>(rowA + nt);
            nB = *reinterpret_cast<const float4*>(rowB + nt);
        }

        const float xsA[4] = {a0.x, a0.y, a0.z, a0.w};
        const float xsB[4] = {b0.x, b0.y, b0.z, b0.w};
        const int nremA = lenA - t0, nremB = lenB - t0;

        if (nremA >= 4 && nremB >= 4) {
#pragma unroll
            for (int k = 0; k < 4; k++)
                lstm_step2(sA, sB, xsA[k], xsB[k], true, true,
                           wihP, wihQ, bsP, bsQ, whhP, whhQ);
        } else {
#pragma unroll
            for (int k = 0; k < 4; k++) {
                if (k < max(nremA, nremB))
                    lstm_step2(sA, sB, xsA[k], xsB[k], k < nremA, k < nremB,
                               wihP, wihQ, bsP, bsQ, whhP, whhQ);
            }
        }
        a0 = nA; b0 = nB;
    }

#pragma unroll
    for (int u = 0; u < HID; u++) {
        out[bA * HID + u] = sA.h[u];
        out[bB * HID + u] = sB.h[u];
    }
}

// ---------------------------------------------------------------------------
extern "C" void kernel_launch(void* const* d_in, const int* in_sizes, int n_in,
                              void* d_out, int out_size) {
    const float* x    = (const float*)d_in[0];
    const float* W_ih = (const float*)d_in[1];
    const float* W_hh = (const float*)d_in[2];
    const float* b_ih = (const float*)d_in[3];
    const float* b_hh = (const float*)d_in[4];
    float* out = (float*)d_out;

    len_kernel<<<BSZ, 256>>>(x);
    lstm_kernel<<<(BSZ / 2) / 64, 64>>>(x, W_ih, W_hh, b_ih, b_hh, out);
}

// round 12
// speedup vs baseline: 2.6346x; 2.6346x over previous
#include <cuda_runtime.h>
#include <cuda_fp16.h>

#define HID 5
#define HDIM 2048
#define BSZ 16384

__device__ int g_lengths[BSZ];

// ---------------------------------------------------------------------------
// Kernel 1: per-row nonzero count (ragged length, matches reference mask)
// ---------------------------------------------------------------------------
__global__ void len_kernel(const float* __restrict__ x) {
    int b = blockIdx.x;
    const float4* row = reinterpret_cast<const float4*>(x + (size_t)b * HDIM);
    int tid = threadIdx.x;
    int cnt = 0;
#pragma unroll
    for (int i = 0; i < 2; i++) {
        float4 v = row[tid + i * 256];
        cnt += (v.x != 0.f) + (v.y != 0.f) + (v.z != 0.f) + (v.w != 0.f);
    }
    __shared__ int s[8];
#pragma unroll
    for (int o = 16; o > 0; o >>= 1) cnt += __shfl_down_sync(0xffffffffu, cnt, o);
    if ((tid & 31) == 0) s[tid >> 5] = cnt;
    __syncthreads();
    if (tid < 8) {
        int v = s[tid];
#pragma unroll
        for (int o = 4; o > 0; o >>= 1) v += __shfl_down_sync(0xffu, v, o);
        if (tid == 0) g_lengths[b] = v;
    }
}

// ---------------------------------------------------------------------------
// math helpers
// ---------------------------------------------------------------------------
__device__ __forceinline__ float fast_tanh(float v) {
    float r; asm("tanh.approx.f32 %0, %1;" : "=f"(r) : "f"(v)); return r;
}
__device__ __forceinline__ __half2 tanh2(__half2 v) {
    unsigned u = *reinterpret_cast<unsigned*>(&v), r;
    asm("tanh.approx.f16x2 %0, %1;" : "=r"(r) : "r"(u));
    return *reinterpret_cast<__half2*>(&r);
}

// ---------------------------------------------------------------------------
// LSTM: 2 sequences per thread, GEMV and epilogue FUSED PER UNIT so only
// 4 half2 accumulators are ever live (no spills), with old/new h double
// buffer. MUFU of unit u overlaps HFMA2 GEMV of unit u+1 in program order.
// Pairs P_u={0.5i,0.5f}, Q_u={0.5o, g}; sigmoids + tanh(g) via f16x2 tanh;
// cn / tanh(cn) / h in fp32. Predicated (SEL) ragged-tail updates.
// ---------------------------------------------------------------------------
struct State {
    __half2 h2[HID];   // fp16 {h,h} for GEMV (read: old, written: new)
    float   c[HID];
    float   h[HID];    // fp32 output path
};

__device__ __forceinline__ void lstm_step2(State& sA, State& sB,
    float xvA, float xvB, bool updA, bool updB,
    const __half2* __restrict__ wihP, const __half2* __restrict__ wihQ,
    const __half2* __restrict__ bsP,  const __half2* __restrict__ bsQ,
    const __half2 (*whhP)[HID], const __half2 (*whhQ)[HID])
{
    const __half2 xA = __float2half2_rn(xvA);
    const __half2 xB = __float2half2_rn(xvB);
    const __half2 h05 = __float2half2_rn(0.5f);

    // snapshot old h (register renames, compiler-free)
    __half2 oA[HID], oB[HID];
#pragma unroll
    for (int j = 0; j < HID; j++) { oA[j] = sA.h2[j]; oB[j] = sB.h2[j]; }

#pragma unroll
    for (int u = 0; u < HID; u++) {
        // --- GEMV for unit u, both seqs (24 HFMA2) ---
        __half2 pa = __hfma2(xA, wihP[u], bsP[u]);
        __half2 qa = __hfma2(xA, wihQ[u], bsQ[u]);
        __half2 pb = __hfma2(xB, wihP[u], bsP[u]);
        __half2 qb = __hfma2(xB, wihQ[u], bsQ[u]);
#pragma unroll
        for (int j = 0; j < HID; j++) {
            pa = __hfma2(oA[j], whhP[u][j], pa);
            qa = __hfma2(oA[j], whhQ[u][j], qa);
            pb = __hfma2(oB[j], whhP[u][j], pb);
            qb = __hfma2(oB[j], whhQ[u][j], qb);
        }
        // --- epilogue unit u, seq A ---
        {
            const __half2 sP = __hfma2(tanh2(pa), h05, h05);  // {ig, fg}
            const __half2 tQ = tanh2(qa);                     // {t(.5o), t(g)}
            const float ig = __low2float(sP);
            const float fg = __high2float(sP);
            const float og = fmaf(__low2float(tQ), 0.5f, 0.5f);
            const float tg = __high2float(tQ);
            const float cn = fmaf(fg, sA.c[u], ig * tg);
            const float hn = og * fast_tanh(cn);
            if (updA) { sA.c[u] = cn; sA.h[u] = hn; sA.h2[u] = __float2half2_rn(hn); }
        }
        // --- epilogue unit u, seq B ---
        {
            const __half2 sP = __hfma2(tanh2(pb), h05, h05);
            const __half2 tQ = tanh2(qb);
            const float ig = __low2float(sP);
            const float fg = __high2float(sP);
            const float og = fmaf(__low2float(tQ), 0.5f, 0.5f);
            const float tg = __high2float(tQ);
            const float cn = fmaf(fg, sB.c[u], ig * tg);
            const float hn = og * fast_tanh(cn);
            if (updB) { sB.c[u] = cn; sB.h[u] = hn; sB.h2[u] = __float2half2_rn(hn); }
        }
    }
}

__global__ void __launch_bounds__(64, 1) lstm_kernel(
    const float* __restrict__ x,
    const float* __restrict__ W_ih,
    const float* __restrict__ W_hh,
    const float* __restrict__ b_ih,
    const float* __restrict__ b_hh,
    float* __restrict__ out)
{
    const int tid = blockIdx.x * blockDim.x + threadIdx.x;
    const int bA = 2 * tid, bB = 2 * tid + 1;

    // gate rows: i:0-4  f:5-9  g:10-14  o:15-19
    __half2 wihP[HID], wihQ[HID], bsP[HID], bsQ[HID];
    __half2 whhP[HID][HID], whhQ[HID][HID];
#pragma unroll
    for (int u = 0; u < HID; u++) {
        const int ri = u, rf = HID + u, rg = 2 * HID + u, ro = 3 * HID + u;
        wihP[u] = __floats2half2_rn(0.5f * W_ih[ri], 0.5f * W_ih[rf]);
        wihQ[u] = __floats2half2_rn(0.5f * W_ih[ro], W_ih[rg]);
        bsP[u]  = __floats2half2_rn(0.5f * (b_ih[ri] + b_hh[ri]),
                                    0.5f * (b_ih[rf] + b_hh[rf]));
        bsQ[u]  = __floats2half2_rn(0.5f * (b_ih[ro] + b_hh[ro]),
                                    (b_ih[rg] + b_hh[rg]));
#pragma unroll
        for (int j = 0; j < HID; j++) {
            whhP[u][j] = __floats2half2_rn(0.5f * W_hh[ri * HID + j],
                                           0.5f * W_hh[rf * HID + j]);
            whhQ[u][j] = __floats2half2_rn(0.5f * W_hh[ro * HID + j],
                                           W_hh[rg * HID + j]);
        }
    }

    const int lenA = g_lengths[bA];
    const int lenB = g_lengths[bB];
    const int lmax = max(lenA, lenB);
    const float* rowA = x + (size_t)bA * HDIM;
    const float* rowB = x + (size_t)bB * HDIM;

    State sA, sB;
#pragma unroll
    for (int u = 0; u < HID; u++) {
        sA.h2[u] = __float2half2_rn(0.f); sA.c[u] = 0.f; sA.h[u] = 0.f;
        sB.h2[u] = __float2half2_rn(0.f); sB.c[u] = 0.f; sB.h[u] = 0.f;
    }

    float4 a0 = make_float4(0.f, 0.f, 0.f, 0.f), b0 = a0;
    if (lmax > 0) {
        a0 = *reinterpret_cast<const float4*>(rowA);
        b0 = *reinterpret_cast<const float4*>(rowB);
    }

    for (int t0 = 0; t0 < lmax; t0 += 4) {
        float4 nA = a0, nB = b0;
        const int nt = t0 + 4;
        if (nt < HDIM) {
            nA = *reinterpret_cast<const float4*>(rowA + nt);
            nB = *reinterpret_cast<const float4*>(rowB + nt);
        }

        const float xsA[4] = {a0.x, a0.y, a0.z, a0.w};
        const float xsB[4] = {b0.x, b0.y, b0.z, b0.w};

#pragma unroll
        for (int k = 0; k < 4; k++) {
            const int t = t0 + k;
            lstm_step2(sA, sB, xsA[k], xsB[k], t < lenA, t < lenB,
                       wihP, wihQ, bsP, bsQ, whhP, whhQ);
        }
        a0 = nA; b0 = nB;
    }

#pragma unroll
    for (int u = 0; u < HID; u++) {
        out[bA * HID + u] = sA.h[u];
        out[bB * HID + u] = sB.h[u];
    }
}

// ---------------------------------------------------------------------------
extern "C" void kernel_launch(void* const* d_in, const int* in_sizes, int n_in,
                              void* d_out, int out_size) {
    const float* x    = (const float*)d_in[0];
    const float* W_ih = (const float*)d_in[1];
    const float* W_hh = (const float*)d_in[2];
    const float* b_ih = (const float*)d_in[3];
    const float* b_hh = (const float*)d_in[4];
    float* out = (float*)d_out;

    len_kernel<<<BSZ, 256>>>(x);
    lstm_kernel<<<(BSZ / 2) / 64, 64>>>(x, W_ih, W_hh, b_ih, b_hh, out);
}

// round 13
// speedup vs baseline: 3.9314x; 1.4922x over previous
#include <cuda_runtime.h>
#include <cuda_fp16.h>

#define HID 5
#define HDIM 2048
#define BSZ 16384

__device__ int g_lengths[BSZ];

// ---------------------------------------------------------------------------
// Kernel 1: per-row nonzero count (ragged length, matches reference mask)
// ---------------------------------------------------------------------------
__global__ void len_kernel(const float* __restrict__ x) {
    int b = blockIdx.x;
    const float4* row = reinterpret_cast<const float4*>(x + (size_t)b * HDIM);
    int tid = threadIdx.x;
    int cnt = 0;
#pragma unroll
    for (int i = 0; i < 2; i++) {
        float4 v = row[tid + i * 256];
        cnt += (v.x != 0.f) + (v.y != 0.f) + (v.z != 0.f) + (v.w != 0.f);
    }
    __shared__ int s[8];
#pragma unroll
    for (int o = 16; o > 0; o >>= 1) cnt += __shfl_down_sync(0xffffffffu, cnt, o);
    if ((tid & 31) == 0) s[tid >> 5] = cnt;
    __syncthreads();
    if (tid < 8) {
        int v = s[tid];
#pragma unroll
        for (int o = 4; o > 0; o >>= 1) v += __shfl_down_sync(0xffu, v, o);
        if (tid == 0) g_lengths[b] = v;
    }
}

// ---------------------------------------------------------------------------
// math helpers
// ---------------------------------------------------------------------------
__device__ __forceinline__ float fast_tanh(float v) {
    float r; asm("tanh.approx.f32 %0, %1;" : "=f"(r) : "f"(v)); return r;
}
__device__ __forceinline__ unsigned tanh2u(unsigned u) {
    unsigned r; asm("tanh.approx.f16x2 %0, %1;" : "=r"(r) : "r"(u)); return r;
}
__device__ __forceinline__ unsigned h2u(__half2 h) { return *reinterpret_cast<unsigned*>(&h); }

// f16 -> f32 widening done with INTEGER ALU ops (exact for normal f16;
// f16 denormals map to <=6e-5 abs error - negligible here). This keeps the
// conversions OFF the MUFU/XU pipe (rt8) and on the ALU pipe (rt2).
__device__ __forceinline__ float wlo(unsigned v) {   // low f16 half of reg
    unsigned m = ((v << 13) & 0x0FFFE000u) + 0x38000000u;
    return __uint_as_float(m | ((v << 16) & 0x80000000u));
}
__device__ __forceinline__ float whi(unsigned v) {   // high f16 half of reg
    unsigned m = ((v >> 3) & 0x0FFFE000u) + 0x38000000u;
    return __uint_as_float(m | (v & 0x80000000u));
}

// ---------------------------------------------------------------------------
// LSTM: 1 thread / sequence (R10 skeleton).
// GEMV fp16 HFMA2, pairs P_u={0.5i,0.5f}, Q_u={0.5o, g}.
// Epilogue: f16x2 tanh -> ALU integer widen -> fp32 cn / tanh(cn) / h.
// ---------------------------------------------------------------------------
struct State {
    __half2 h2[HID];   // {h_j, h_j} fp16 for the GEMV
    float   c[HID];
    float   h[HID];
};

__device__ __forceinline__ void lstm_step(State& st, float xv,
    const __half2* __restrict__ wihP, const __half2* __restrict__ wihQ,
    const __half2* __restrict__ bsP,  const __half2* __restrict__ bsQ,
    const __half2 (*whhP)[HID], const __half2 (*whhQ)[HID])
{
    const __half2 x2 = __float2half2_rn(xv);
    __half2 aP[HID], aQ[HID];
#pragma unroll
    for (int u = 0; u < HID; u++) {
        __half2 a = __hfma2(x2, wihP[u], bsP[u]);
        __half2 b = __hfma2(x2, wihQ[u], bsQ[u]);
#pragma unroll
        for (int j = 0; j < HID; j++) {
            a = __hfma2(st.h2[j], whhP[u][j], a);
            b = __hfma2(st.h2[j], whhQ[u][j], b);
        }
        aP[u] = a; aQ[u] = b;
    }
#pragma unroll
    for (int u = 0; u < HID; u++) {
        const unsigned tp = tanh2u(h2u(aP[u]));   // {t(.5zi), t(.5zf)}
        const unsigned tq = tanh2u(h2u(aQ[u]));   // {t(.5zo), t(zg)}
        const float ig = fmaf(wlo(tp), 0.5f, 0.5f);
        const float fg = fmaf(whi(tp), 0.5f, 0.5f);
        const float og = fmaf(wlo(tq), 0.5f, 0.5f);
        const float tg = whi(tq);                 // tanh(g), f16-quantized
        const float cn = fmaf(fg, st.c[u], ig * tg);
        st.c[u] = cn;
        const float hn = og * fast_tanh(cn);      // fp32 tanh(c)
        st.h[u]  = hn;
        st.h2[u] = __float2half2_rn(hn);
    }
}

__global__ void __launch_bounds__(64, 1) lstm_kernel(
    const float* __restrict__ x,
    const float* __restrict__ W_ih,
    const float* __restrict__ W_hh,
    const float* __restrict__ b_ih,
    const float* __restrict__ b_hh,
    float* __restrict__ out)
{
    int b = blockIdx.x * blockDim.x + threadIdx.x;

    // gate rows: i:0-4  f:5-9  g:10-14  o:15-19
    __half2 wihP[HID], wihQ[HID], bsP[HID], bsQ[HID];
    __half2 whhP[HID][HID], whhQ[HID][HID];
#pragma unroll
    for (int u = 0; u < HID; u++) {
        const int ri = u, rf = HID + u, rg = 2 * HID + u, ro = 3 * HID + u;
        wihP[u] = __floats2half2_rn(0.5f * W_ih[ri], 0.5f * W_ih[rf]);
        wihQ[u] = __floats2half2_rn(0.5f * W_ih[ro], W_ih[rg]);
        bsP[u]  = __floats2half2_rn(0.5f * (b_ih[ri] + b_hh[ri]),
                                    0.5f * (b_ih[rf] + b_hh[rf]));
        bsQ[u]  = __floats2half2_rn(0.5f * (b_ih[ro] + b_hh[ro]),
                                    (b_ih[rg] + b_hh[rg]));
#pragma unroll
        for (int j = 0; j < HID; j++) {
            whhP[u][j] = __floats2half2_rn(0.5f * W_hh[ri * HID + j],
                                           0.5f * W_hh[rf * HID + j]);
            whhQ[u][j] = __floats2half2_rn(0.5f * W_hh[ro * HID + j],
                                           W_hh[rg * HID + j]);
        }
    }

    const int len = g_lengths[b];
    const float* row = x + (size_t)b * HDIM;

    State st;
#pragma unroll
    for (int u = 0; u < HID; u++) {
        st.h2[u] = __float2half2_rn(0.f);
        st.c[u] = 0.f;
        st.h[u] = 0.f;
    }

    float4 a0 = make_float4(0.f, 0.f, 0.f, 0.f);
    if (len > 0) a0 = *reinterpret_cast<const float4*>(row);

    for (int t0 = 0; t0 < len; t0 += 4) {
        // prefetch next 4 timesteps (HDIM multiple of 4)
        float4 nx = a0;
        const int nt = t0 + 4;
        if (nt < HDIM) nx = *reinterpret_cast<const float4*>(row + nt);

        const int nrem = len - t0;
        if (nrem >= 4) {
            lstm_step(st, a0.x, wihP, wihQ, bsP, bsQ, whhP, whhQ);
            lstm_step(st, a0.y, wihP, wihQ, bsP, bsQ, whhP, whhQ);
            lstm_step(st, a0.z, wihP, wihQ, bsP, bsQ, whhP, whhQ);
            lstm_step(st, a0.w, wihP, wihQ, bsP, bsQ, whhP, whhQ);
        } else {
            float xs[4] = {a0.x, a0.y, a0.z, a0.w};
#pragma unroll
            for (int k = 0; k < 4; k++)
                if (k < nrem)
                    lstm_step(st, xs[k], wihP, wihQ, bsP, bsQ, whhP, whhQ);
        }
        a0 = nx;
    }

#pragma unroll
    for (int u = 0; u < HID; u++) out[b * HID + u] = st.h[u];
}

// ---------------------------------------------------------------------------
extern "C" void kernel_launch(void* const* d_in, const int* in_sizes, int n_in,
                              void* d_out, int out_size) {
    const float* x    = (const float*)d_in[0];
    const float* W_ih = (const float*)d_in[1];
    const float* W_hh = (const float*)d_in[2];
    const float* b_ih = (const float*)d_in[3];
    const float* b_hh = (const float*)d_in[4];
    float* out = (float*)d_out;

    len_kernel<<<BSZ, 256>>>(x);
    lstm_kernel<<<BSZ / 64, 64>>>(x, W_ih, W_hh, b_ih, b_hh, out);
}

// round 14
// speedup vs baseline: 4.9767x; 1.2659x over previous
#include <cuda_runtime.h>
#include <cuda_fp16.h>

#define HID 5
#define HDIM 2048
#define BSZ 16384

__device__ int g_lengths[BSZ];

// ---------------------------------------------------------------------------
// Kernel 1: per-row nonzero count (ragged length, matches reference mask)
// ---------------------------------------------------------------------------
__global__ void len_kernel(const float* __restrict__ x) {
    int b = blockIdx.x;
    const float4* row = reinterpret_cast<const float4*>(x + (size_t)b * HDIM);
    int tid = threadIdx.x;
    int cnt = 0;
#pragma unroll
    for (int i = 0; i < 2; i++) {
        float4 v = row[tid + i * 256];
        cnt += (v.x != 0.f) + (v.y != 0.f) + (v.z != 0.f) + (v.w != 0.f);
    }
    __shared__ int s[8];
#pragma unroll
    for (int o = 16; o > 0; o >>= 1) cnt += __shfl_down_sync(0xffffffffu, cnt, o);
    if ((tid & 31) == 0) s[tid >> 5] = cnt;
    __syncthreads();
    if (tid < 8) {
        int v = s[tid];
#pragma unroll
        for (int o = 4; o > 0; o >>= 1) v += __shfl_down_sync(0xffu, v, o);
        if (tid == 0) g_lengths[b] = v;
    }
}

// ---------------------------------------------------------------------------
// math helpers
// ---------------------------------------------------------------------------
__device__ __forceinline__ float fast_tanh(float v) {
    float r; asm("tanh.approx.f32 %0, %1;" : "=f"(r) : "f"(v)); return r;
}
__device__ __forceinline__ __half2 tanh2(__half2 v) {
    unsigned u = *reinterpret_cast<unsigned*>(&v), r;
    asm("tanh.approx.f16x2 %0, %1;" : "=r"(r) : "r"(u));
    return *reinterpret_cast<__half2*>(&r);
}

// ---------------------------------------------------------------------------
// LSTM, sub-step software-pipelined: gate accumulators for step t+1 are
// built INSIDE step t's epilogue (column-u HFMA2s fire right after unit u's
// h commits), so the fma stream interleaves with the MUFU stream instead of
// serializing behind it. Pairs P_u={0.5i,0.5f}, Q_u={0.5o, g};
// sigmoids + tanh(g) via f16x2 tanh; cn / tanh(cn) / h in fp32.
// Accumulation order (x, then h_0..h_4) identical to R10 -> same numerics.
// ---------------------------------------------------------------------------
struct State {
    float c[HID];
    float h[HID];
};

// One step: consumes accP/accQ (gates of step t), produces h/c, and builds
// nxtP/nxtQ = gates of step t+1 seeded from xnext. upd gates the commit.
__device__ __forceinline__ void lstm_step(State& st,
    __half2* accP, __half2* accQ, float xnext, bool upd,
    const __half2* __restrict__ wihP, const __half2* __restrict__ wihQ,
    const __half2* __restrict__ bsP,  const __half2* __restrict__ bsQ,
    const __half2 (*whhP)[HID], const __half2 (*whhQ)[HID])
{
    const __half2 xn = __float2half2_rn(xnext);
    __half2 nxtP[HID], nxtQ[HID];
#pragma unroll
    for (int p = 0; p < HID; p++) {
        nxtP[p] = __hfma2(xn, wihP[p], bsP[p]);
        nxtQ[p] = __hfma2(xn, wihQ[p], bsQ[p]);
    }

    const __half2 h05 = __float2half2_rn(0.5f);
#pragma unroll
    for (int u = 0; u < HID; u++) {
        const __half2 tP = tanh2(accP[u]);            // {t(.5zi), t(.5zf)}
        const __half2 tQ = tanh2(accQ[u]);            // {t(.5zo), t(zg)}
        const __half2 sP = __hfma2(tP, h05, h05);     // {ig, fg}
        const float ig = __low2float(sP);
        const float fg = __high2float(sP);
        const float og = fmaf(__low2float(tQ), 0.5f, 0.5f);
        const float tg = __high2float(tQ);
        const float cn = fmaf(fg, st.c[u], ig * tg);
        const float hn = og * fast_tanh(cn);
        const float hc = upd ? hn : st.h[u];          // committed h
        if (upd) { st.c[u] = cn; st.h[u] = hn; }
        const __half2 hb = __float2half2_rn(hc);      // broadcast {h,h}
        // fold column u into next step's gates immediately (10 HFMA2)
#pragma unroll
        for (int p = 0; p < HID; p++) {
            nxtP[p] = __hfma2(hb, whhP[p][u], nxtP[p]);
            nxtQ[p] = __hfma2(hb, whhQ[p][u], nxtQ[p]);
        }
    }
#pragma unroll
    for (int p = 0; p < HID; p++) { accP[p] = nxtP[p]; accQ[p] = nxtQ[p]; }
}

__global__ void __launch_bounds__(64, 1) lstm_kernel(
    const float* __restrict__ x,
    const float* __restrict__ W_ih,
    const float* __restrict__ W_hh,
    const float* __restrict__ b_ih,
    const float* __restrict__ b_hh,
    float* __restrict__ out)
{
    int b = blockIdx.x * blockDim.x + threadIdx.x;

    // gate rows: i:0-4  f:5-9  g:10-14  o:15-19
    __half2 wihP[HID], wihQ[HID], bsP[HID], bsQ[HID];
    __half2 whhP[HID][HID], whhQ[HID][HID];   // [pair][column j]
#pragma unroll
    for (int u = 0; u < HID; u++) {
        const int ri = u, rf = HID + u, rg = 2 * HID + u, ro = 3 * HID + u;
        wihP[u] = __floats2half2_rn(0.5f * W_ih[ri], 0.5f * W_ih[rf]);
        wihQ[u] = __floats2half2_rn(0.5f * W_ih[ro], W_ih[rg]);
        bsP[u]  = __floats2half2_rn(0.5f * (b_ih[ri] + b_hh[ri]),
                                    0.5f * (b_ih[rf] + b_hh[rf]));
        bsQ[u]  = __floats2half2_rn(0.5f * (b_ih[ro] + b_hh[ro]),
                                    (b_ih[rg] + b_hh[rg]));
#pragma unroll
        for (int j = 0; j < HID; j++) {
            whhP[u][j] = __floats2half2_rn(0.5f * W_hh[ri * HID + j],
                                           0.5f * W_hh[rf * HID + j]);
            whhQ[u][j] = __floats2half2_rn(0.5f * W_hh[ro * HID + j],
                                           W_hh[rg * HID + j]);
        }
    }

    const int len = g_lengths[b];
    const float* row = x + (size_t)b * HDIM;

    State st;
#pragma unroll
    for (int u = 0; u < HID; u++) { st.c[u] = 0.f; st.h[u] = 0.f; }

    float4 a0 = make_float4(0.f, 0.f, 0.f, 0.f);
    if (len > 0) a0 = *reinterpret_cast<const float4*>(row);

    // prologue: gates for t=0 (h=0 -> just bias + x0*wih)
    __half2 accP[HID], accQ[HID];
    {
        const __half2 x0 = __float2half2_rn(a0.x);
#pragma unroll
        for (int p = 0; p < HID; p++) {
            accP[p] = __hfma2(x0, wihP[p], bsP[p]);
            accQ[p] = __hfma2(x0, wihQ[p], bsQ[p]);
        }
    }

    for (int t0 = 0; t0 < len; t0 += 4) {
        // prefetch next 4 timesteps (HDIM multiple of 4)
        float4 nx = a0;
        const int nt = t0 + 4;
        if (nt < HDIM) nx = *reinterpret_cast<const float4*>(row + nt);

        const int nrem = len - t0;
        if (nrem >= 4) {
            lstm_step(st, accP, accQ, a0.y, true, wihP, wihQ, bsP, bsQ, whhP, whhQ);
            lstm_step(st, accP, accQ, a0.z, true, wihP, wihQ, bsP, bsQ, whhP, whhQ);
            lstm_step(st, accP, accQ, a0.w, true, wihP, wihQ, bsP, bsQ, whhP, whhQ);
            lstm_step(st, accP, accQ, nx.x, true, wihP, wihQ, bsP, bsQ, whhP, whhQ);
        } else {
            const float xn[4] = {a0.y, a0.z, a0.w, nx.x};
#pragma unroll
            for (int k = 0; k < 4; k++)
                lstm_step(st, accP, accQ, xn[k], k < nrem,
                          wihP, wihQ, bsP, bsQ, whhP, whhQ);
        }
        a0 = nx;
    }

#pragma unroll
    for (int u = 0; u < HID; u++) out[b * HID + u] = st.h[u];
}

// ---------------------------------------------------------------------------
extern "C" void kernel_launch(void* const* d_in, const int* in_sizes, int n_in,
                              void* d_out, int out_size) {
    const float* x    = (const float*)d_in[0];
    const float* W_ih = (const float*)d_in[1];
    const float* W_hh = (const float*)d_in[2];
    const float* b_ih = (const float*)d_in[3];
    const float* b_hh = (const float*)d_in[4];
    float* out = (float*)d_out;

    len_kernel<<<BSZ, 256>>>(x);
    lstm_kernel<<<BSZ / 64, 64>>>(x, W_ih, W_hh, b_ih, b_hh, out);
}